// round 2
// baseline (speedup 1.0000x reference)
#include <cuda_runtime.h>
#include <math.h>

#define T_DIM 1024
#define B_DIM 4
#define E_DIM 1024
#define H_DIM 16
#define D_DIM 64
#define RANK_ 4
#define E3 (3*E_DIM)

// ---- device scratch (allowed; no runtime allocation) ----
__device__ float g_w_in [E_DIM*E3];
__device__ float g_w_pos[E_DIM*E_DIM];
__device__ float g_w_out[E_DIM*E_DIM];
__device__ float g_qkv  [T_DIM*B_DIM*E3];
__device__ float g_rk   [T_DIM*E_DIM];
__device__ float g_ctx  [T_DIM*B_DIM*E_DIM];

// ---- W' = W + sum_r outer(r[lang,r,:E], s[lang,r,:F]) ----
__global__ void build_w_kernel(const float* __restrict__ base, const float* __restrict__ rfac,
                               const float* __restrict__ sfac, const int* __restrict__ idx,
                               float* __restrict__ out, int F) {
    int lang = idx[0];
    long i = (long)blockIdx.x * blockDim.x + threadIdx.x;
    long total = (long)E_DIM * F;
    if (i >= total) return;
    int e = (int)(i / F), f = (int)(i % F);
    const float* rp = rfac + (long)lang * RANK_ * E_DIM;
    const float* sp = sfac + (long)lang * RANK_ * F;
    float acc = base[i];
#pragma unroll
    for (int r = 0; r < RANK_; r++) acc += rp[r*E_DIM + e] * sp[(long)r*F + f];
    out[i] = acc;
}

// ---- C[M,N] = A[M,K] @ B[K,N] + bias[N]; all dims multiples of 64 ----
__global__ void sgemm_bias_kernel(const float* __restrict__ A, const float* __restrict__ Bm,
                                  const float* __restrict__ bias, float* __restrict__ C,
                                  int M, int N, int K) {
    __shared__ float As[64][16];
    __shared__ float Bs[16][64];
    int tx = threadIdx.x, ty = threadIdx.y;
    int tid = ty*16 + tx;
    int m0 = blockIdx.y*64, n0 = blockIdx.x*64;
    float acc[4][4] = {};
    for (int k0 = 0; k0 < K; k0 += 16) {
#pragma unroll
        for (int l = 0; l < 4; l++) {
            int e = tid + 256*l;
            int mm = e >> 4, kk = e & 15;
            As[mm][kk] = A[(long)(m0+mm)*K + k0 + kk];
            int bk = e >> 6, nn = e & 63;
            Bs[bk][nn] = Bm[(long)(k0+bk)*N + n0 + nn];
        }
        __syncthreads();
#pragma unroll
        for (int kk = 0; kk < 16; kk++) {
            float a[4], b[4];
#pragma unroll
            for (int r = 0; r < 4; r++) a[r] = As[ty*4+r][kk];
#pragma unroll
            for (int c = 0; c < 4; c++) b[c] = Bs[kk][tx*4+c];
#pragma unroll
            for (int r = 0; r < 4; r++)
#pragma unroll
                for (int c = 0; c < 4; c++)
                    acc[r][c] = fmaf(a[r], b[c], acc[r][c]);
        }
        __syncthreads();
    }
#pragma unroll
    for (int r = 0; r < 4; r++)
#pragma unroll
        for (int c = 0; c < 4; c++) {
            int m = m0 + ty*4 + r, n = n0 + tx*4 + c;
            C[(long)m*N + n] = acc[r][c] + bias[n];
        }
}

// ---- fused relative attention (flash-style, per (b,h,64-row Q tile)) ----
// delta = j - i:
//   delta <= 0 : s += (q_i   + rrb) . rk[T-1+delta]
//   delta == 1 : s += 0
//   delta >= 2 : s += (q_{i+1}+rrb) . rk[delta-2]
__global__ void attn_kernel(const float* __restrict__ qkv, const float* __restrict__ rk,
                            const unsigned char* __restrict__ mask,
                            const float* __restrict__ rwb, const float* __restrict__ rrb,
                            float* __restrict__ ctx) {
    extern __shared__ float sm[];
    float* qw  = sm;            // 64*64
    float* qr  = qw  + 4096;    // 65*64  (rows i0..i0+64)
    float* kt  = qr  + 4160;    // 64*64
    float* vt  = kt  + 4096;    // 64*64
    float* rks = vt  + 4096;    // 127*64 (delta-indexed rk window)
    float* ps  = rks + 8128;    // 64*64 (softmax probs)

    int tx = threadIdx.x, ty = threadIdx.y;
    int tid = ty*16 + tx;
    int i0 = blockIdx.x*64;
    int h = blockIdx.y, b = blockIdx.z;
    const float scale = 0.125f;

    // Q tile: qw rows 0..63 (with r_w_bias), qr rows 0..64 (with r_r_bias)
    for (int e = tid; e < 4160; e += 256) {
        int ii = e >> 6, d = e & 63;
        int t = i0 + ii;
        float qv = (t < T_DIM) ? qkv[(long)(t*B_DIM + b)*E3 + h*D_DIM + d] : 0.f;
        if (ii < 64) qw[e] = qv + rwb[h*D_DIM + d];
        qr[e] = qv + rrb[h*D_DIM + d];
    }

    float m[4], l[4], acc[4][4];
#pragma unroll
    for (int r = 0; r < 4; r++) {
        m[r] = -1e30f; l[r] = 0.f;
#pragma unroll
        for (int c = 0; c < 4; c++) acc[r][c] = 0.f;
    }

    const int rbase = 63 + 4*(tx - ty);  // window slot where delta = j0 - i0

    for (int j0 = 0; j0 < T_DIM; j0 += 64) {
        __syncthreads();  // previous iter's PV done before reloading tiles
        for (int e = tid; e < 4096; e += 256) {
            int jj = e >> 6, d = e & 63;
            long off = (long)((j0+jj)*B_DIM + b)*E3 + h*D_DIM + d;
            kt[e] = qkv[off + E_DIM];
            vt[e] = qkv[off + 2*E_DIM];
        }
        // rk window: slot w covers delta = base - 63 + w, w in [0,126]
        int base = j0 - i0;
        for (int e = tid; e < 8128; e += 256) {
            int w = e >> 6, d = e & 63;
            int delta = base - 63 + w;
            float v;
            if (delta <= 0)      v = rk[(long)(T_DIM - 1 + delta)*E_DIM + h*D_DIM + d];
            else if (delta == 1) v = 0.f;
            else                 v = rk[(long)(delta - 2)*E_DIM + h*D_DIM + d];
            rks[e] = v;
        }
        __syncthreads();

        float s[4][4];
#pragma unroll
        for (int r = 0; r < 4; r++)
#pragma unroll
            for (int c = 0; c < 4; c++) s[r][c] = 0.f;

        const int d0 = base + 4*(tx - ty);  // delta at (r=c)

        for (int d = 0; d < 64; d++) {
            float aw[4], ar[5], bk[4], rv[7];
#pragma unroll
            for (int r = 0; r < 4; r++) aw[r] = qw[(ty*4+r)*64 + d];
#pragma unroll
            for (int k = 0; k < 5; k++) ar[k] = qr[(ty*4+k)*64 + d];
#pragma unroll
            for (int c = 0; c < 4; c++) bk[c] = kt[(tx*4+c)*64 + d];
#pragma unroll
            for (int o = 0; o < 7; o++) rv[o] = rks[(rbase + o - 3)*64 + d];
#pragma unroll
            for (int r = 0; r < 4; r++)
#pragma unroll
                for (int c = 0; c < 4; c++) {
                    float av = (d0 + c - r <= 0) ? ar[r] : ar[r+1];
                    s[r][c] += aw[r]*bk[c] + av*rv[c - r + 3];
                }
        }

        // scale + key padding mask
#pragma unroll
        for (int c = 0; c < 4; c++) {
            bool mk = mask[b*T_DIM + j0 + tx*4 + c] != 0;
#pragma unroll
            for (int r = 0; r < 4; r++) {
                s[r][c] *= scale;
                if (mk) s[r][c] = -1e9f;
            }
        }

        // online softmax; row owned by the 16 threads sharing ty (half-warp)
#pragma unroll
        for (int r = 0; r < 4; r++) {
            float mx = s[r][0];
#pragma unroll
            for (int c = 1; c < 4; c++) mx = fmaxf(mx, s[r][c]);
#pragma unroll
            for (int off = 8; off >= 1; off >>= 1)
                mx = fmaxf(mx, __shfl_xor_sync(0xffffffffu, mx, off, 16));
            float mnew = fmaxf(m[r], mx);
            float corr = __expf(m[r] - mnew);
            float rs = 0.f;
#pragma unroll
            for (int c = 0; c < 4; c++) {
                float p = __expf(s[r][c] - mnew);
                ps[(ty*4+r)*64 + tx*4 + c] = p;
                rs += p;
            }
#pragma unroll
            for (int off = 8; off >= 1; off >>= 1)
                rs += __shfl_xor_sync(0xffffffffu, rs, off, 16);
            l[r] = l[r]*corr + rs;
            m[r] = mnew;
#pragma unroll
            for (int c = 0; c < 4; c++) acc[r][c] *= corr;
        }
        __syncthreads();

        // PV accumulate
        for (int jj = 0; jj < 64; jj++) {
            float pv[4], vv[4];
#pragma unroll
            for (int r = 0; r < 4; r++) pv[r] = ps[(ty*4+r)*64 + jj];
#pragma unroll
            for (int c = 0; c < 4; c++) vv[c] = vt[jj*64 + tx*4 + c];
#pragma unroll
            for (int r = 0; r < 4; r++)
#pragma unroll
                for (int c = 0; c < 4; c++)
                    acc[r][c] = fmaf(pv[r], vv[c], acc[r][c]);
        }
    }

#pragma unroll
    for (int r = 0; r < 4; r++) {
        float inv = 1.f / l[r];
        int t = i0 + ty*4 + r;
#pragma unroll
        for (int c = 0; c < 4; c++)
            ctx[(long)(t*B_DIM + b)*E_DIM + h*D_DIM + tx*4 + c] = acc[r][c]*inv;
    }
}

extern "C" void kernel_launch(void* const* d_in, const int* in_sizes, int n_in,
                              void* d_out, int out_size) {
    const float* input   = (const float*)d_in[0];
    const float* pos     = (const float*)d_in[1];
    const int*   indices = (const int*)  d_in[2];
    const unsigned char* mask = (const unsigned char*)d_in[3];
    const float* in_w  = (const float*)d_in[4];
    const float* pos_w = (const float*)d_in[5];
    const float* out_w = (const float*)d_in[6];
    const float* in_b  = (const float*)d_in[7];
    const float* pos_b = (const float*)d_in[8];
    const float* out_b = (const float*)d_in[9];
    const float* r_i = (const float*)d_in[10];
    const float* s_i = (const float*)d_in[11];
    const float* r_p = (const float*)d_in[12];
    const float* s_p = (const float*)d_in[13];
    const float* r_o = (const float*)d_in[14];
    const float* s_o = (const float*)d_in[15];
    const float* rwb = (const float*)d_in[16];
    const float* rrb = (const float*)d_in[17];
    float* out = (float*)d_out;

    float *w_in, *w_pos, *w_out, *qkv, *rk, *ctx;
    cudaGetSymbolAddress((void**)&w_in,  g_w_in);
    cudaGetSymbolAddress((void**)&w_pos, g_w_pos);
    cudaGetSymbolAddress((void**)&w_out, g_w_out);
    cudaGetSymbolAddress((void**)&qkv,   g_qkv);
    cudaGetSymbolAddress((void**)&rk,    g_rk);
    cudaGetSymbolAddress((void**)&ctx,   g_ctx);

    const int thr = 256;
    build_w_kernel<<<(E_DIM*E3 + thr - 1)/thr, thr>>>(in_w,  r_i, s_i, indices, w_in,  E3);
    build_w_kernel<<<(E_DIM*E_DIM + thr - 1)/thr, thr>>>(pos_w, r_p, s_p, indices, w_pos, E_DIM);
    build_w_kernel<<<(E_DIM*E_DIM + thr - 1)/thr, thr>>>(out_w, r_o, s_o, indices, w_out, E_DIM);

    dim3 blk(16, 16);
    // qkv = input @ w_in + bias   [4096,1024]x[1024,3072]
    sgemm_bias_kernel<<<dim3(E3/64, (T_DIM*B_DIM)/64), blk>>>(input, w_in, in_b, qkv,
                                                              T_DIM*B_DIM, E3, E_DIM);
    // r_head_k = pos @ w_pos + bias  [1024,1024]x[1024,1024]
    sgemm_bias_kernel<<<dim3(E_DIM/64, T_DIM/64), blk>>>(pos, w_pos, pos_b, rk,
                                                         T_DIM, E_DIM, E_DIM);
    // fused relative attention
    cudaFuncSetAttribute(attn_kernel, cudaFuncAttributeMaxDynamicSharedMemorySize, 114688);
    attn_kernel<<<dim3(T_DIM/64, H_DIM, B_DIM), blk, 114688>>>(qkv, rk, mask, rwb, rrb, ctx);

    // out = ctx @ w_out + bias   [4096,1024]x[1024,1024]
    sgemm_bias_kernel<<<dim3(E_DIM/64, (T_DIM*B_DIM)/64), blk>>>(ctx, w_out, out_b, out,
                                                                 T_DIM*B_DIM, E_DIM, E_DIM);
}

// round 7
// speedup vs baseline: 3.2284x; 3.2284x over previous
#include <cuda_runtime.h>
#include <math.h>

#define T_DIM 1024
#define B_DIM 4
#define E_DIM 1024
#define H_DIM 16
#define D_DIM 64
#define RANK_ 4
#define E3 (3*E_DIM)

// ---- device scratch ----
__device__ float g_w_in [E_DIM*E3];
__device__ float g_w_pos[E_DIM*E_DIM];
__device__ float g_w_out[E_DIM*E_DIM];
__device__ float g_qkv  [T_DIM*B_DIM*E3];
__device__ float g_rk   [T_DIM*E_DIM];
__device__ float g_ctx  [T_DIM*B_DIM*E_DIM];

// ---- W' = W + sum_r outer(r,s) ----
__global__ void build_w_kernel(const float* __restrict__ base, const float* __restrict__ rfac,
                               const float* __restrict__ sfac, const int* __restrict__ idx,
                               float* __restrict__ out, int F) {
    int lang = idx[0];
    long i = (long)blockIdx.x * blockDim.x + threadIdx.x;
    long total = (long)E_DIM * F;
    if (i >= total) return;
    int e = (int)(i / F), f = (int)(i % F);
    const float* rp = rfac + (long)lang * RANK_ * E_DIM;
    const float* sp = sfac + (long)lang * RANK_ * F;
    float acc = base[i];
#pragma unroll
    for (int r = 0; r < RANK_; r++) acc += rp[r*E_DIM + e] * sp[(long)r*F + f];
    out[i] = acc;
}

// ---- C[M,N] = A[M,K] @ B[K,N] + bias[N] ----
__global__ void sgemm_bias_kernel(const float* __restrict__ A, const float* __restrict__ Bm,
                                  const float* __restrict__ bias, float* __restrict__ C,
                                  int M, int N, int K) {
    __shared__ float As[64][16];
    __shared__ float Bs[16][64];
    int tx = threadIdx.x, ty = threadIdx.y;
    int tid = ty*16 + tx;
    int m0 = blockIdx.y*64, n0 = blockIdx.x*64;
    float acc[4][4] = {};
    for (int k0 = 0; k0 < K; k0 += 16) {
#pragma unroll
        for (int l = 0; l < 4; l++) {
            int e = tid + 256*l;
            int mm = e >> 4, kk = e & 15;
            As[mm][kk] = A[(long)(m0+mm)*K + k0 + kk];
            int bk = e >> 6, nn = e & 63;
            Bs[bk][nn] = Bm[(long)(k0+bk)*N + n0 + nn];
        }
        __syncthreads();
#pragma unroll
        for (int kk = 0; kk < 16; kk++) {
            float a[4], b[4];
#pragma unroll
            for (int r = 0; r < 4; r++) a[r] = As[ty*4+r][kk];
#pragma unroll
            for (int c = 0; c < 4; c++) b[c] = Bs[kk][tx*4+c];
#pragma unroll
            for (int r = 0; r < 4; r++)
#pragma unroll
                for (int c = 0; c < 4; c++)
                    acc[r][c] = fmaf(a[r], b[c], acc[r][c]);
        }
        __syncthreads();
    }
#pragma unroll
    for (int r = 0; r < 4; r++)
#pragma unroll
        for (int c = 0; c < 4; c++) {
            int m = m0 + ty*4 + r, n = n0 + tx*4 + c;
            C[(long)m*N + n] = acc[r][c] + bias[n];
        }
}

// ---- fused relative attention, transposed (d-major) smem tiles ----
// delta = j - i:
//   delta <= 0 : s += (q_i   + rrb) . rk[T-1+delta]
//   delta == 1 : s += 0
//   delta >= 2 : s += (q_{i+1}+rrb) . rk[delta-2]
#define QSTR 68     // row stride (floats) for qw/qr/kt (d-major, lane-contig i/j)
#define RSTR 132    // row stride for rks (d-major, 127 window slots)

__global__ __launch_bounds__(256, 2)
void attn_kernel(const float* __restrict__ qkv, const float* __restrict__ rk,
                 const unsigned char* __restrict__ mask,
                 const float* __restrict__ rwb, const float* __restrict__ rrb,
                 float* __restrict__ ctx) {
    extern __shared__ float sm[];
    float* qw  = sm;                 // [64 d][QSTR]  cols ii 0..63
    float* qr  = qw  + 64*QSTR;      // [64 d][QSTR]  cols ii 0..64
    float* kt  = qr  + 64*QSTR;      // [64 d][QSTR]  cols jj 0..63 ; reused as ps
    float* vt  = kt  + 64*QSTR;      // [64 jj][64 c] row-major
    float* rks = vt  + 4096;         // [64 d][RSTR]  cols w 0..126
    float* ps  = kt;                 // overlay: [64 i][QSTR] probs

    int tx = threadIdx.x, ty = threadIdx.y;
    int tid = ty*16 + tx;
    int i0 = blockIdx.x*64;
    int h = blockIdx.y, b = blockIdx.z;
    const float scale = 0.125f;

    // Q tiles (transposed write): 65 rows x 64 d, float4 global loads
    for (int e = tid; e < 65*16; e += 256) {
        int ii = e >> 4, d4 = (e & 15) * 4;
        int t = i0 + ii;
        float4 qv = make_float4(0.f,0.f,0.f,0.f);
        if (t < T_DIM)
            qv = *(const float4*)&qkv[(long)(t*B_DIM + b)*E3 + h*D_DIM + d4];
        float4 wb = *(const float4*)&rwb[h*D_DIM + d4];
        float4 rb = *(const float4*)&rrb[h*D_DIM + d4];
        if (ii < 64) {
            qw[(d4+0)*QSTR + ii] = qv.x + wb.x;
            qw[(d4+1)*QSTR + ii] = qv.y + wb.y;
            qw[(d4+2)*QSTR + ii] = qv.z + wb.z;
            qw[(d4+3)*QSTR + ii] = qv.w + wb.w;
        }
        qr[(d4+0)*QSTR + ii] = qv.x + rb.x;
        qr[(d4+1)*QSTR + ii] = qv.y + rb.y;
        qr[(d4+2)*QSTR + ii] = qv.z + rb.z;
        qr[(d4+3)*QSTR + ii] = qv.w + rb.w;
    }

    float m[4], l[4], acc[4][4];
#pragma unroll
    for (int r = 0; r < 4; r++) {
        m[r] = -1e30f; l[r] = 0.f;
#pragma unroll
        for (int c = 0; c < 4; c++) acc[r][c] = 0.f;
    }

    const int mm15 = 15 + tx - ty;       // window float4 index: w = 4*mm15 covers delta at (r=c)-3

    for (int j0 = 0; j0 < T_DIM; j0 += 64) {
        __syncthreads();  // prev PV reads done before overwriting tiles
        // K (transposed) + V (row-major)
        for (int e = tid; e < 64*16; e += 256) {
            int jj = e >> 4, d4 = (e & 15) * 4;
            long off = (long)((j0+jj)*B_DIM + b)*E3 + h*D_DIM + d4;
            float4 kv = *(const float4*)&qkv[off + E_DIM];
            float4 vv = *(const float4*)&qkv[off + 2*E_DIM];
            kt[(d4+0)*QSTR + jj] = kv.x;
            kt[(d4+1)*QSTR + jj] = kv.y;
            kt[(d4+2)*QSTR + jj] = kv.z;
            kt[(d4+3)*QSTR + jj] = kv.w;
            *(float4*)&vt[jj*64 + d4] = vv;
        }
        // rk window (transposed): slot w covers delta = base - 63 + w
        int base = j0 - i0;
        for (int e = tid; e < 127*16; e += 256) {
            int w = e >> 4, d4 = (e & 15) * 4;
            int delta = base - 63 + w;
            float4 v = make_float4(0.f,0.f,0.f,0.f);
            if (delta <= 0)      v = *(const float4*)&rk[(long)(T_DIM - 1 + delta)*E_DIM + h*D_DIM + d4];
            else if (delta >= 2) v = *(const float4*)&rk[(long)(delta - 2)*E_DIM + h*D_DIM + d4];
            rks[(d4+0)*RSTR + w] = v.x;
            rks[(d4+1)*RSTR + w] = v.y;
            rks[(d4+2)*RSTR + w] = v.z;
            rks[(d4+3)*RSTR + w] = v.w;
        }
        __syncthreads();

        float s[4][4];
#pragma unroll
        for (int r = 0; r < 4; r++)
#pragma unroll
            for (int c = 0; c < 4; c++) s[r][c] = 0.f;

        const int d0 = base + 4*(tx - ty);  // delta at (r=c)

        for (int d = 0; d < 64; d++) {
            float4 aw = *(float4*)&qw[d*QSTR + ty*4];
            float4 a4 = *(float4*)&qr[d*QSTR + ty*4];
            float  a5 = qr[d*QSTR + ty*4 + 4];
            float4 bk = *(float4*)&kt[d*QSTR + tx*4];
            float4 r0 = *(float4*)&rks[d*RSTR + 4*mm15];       // rv[0..3] (o-3 = -3..0)
            float4 r1 = *(float4*)&rks[d*RSTR + 4*mm15 + 4];   // rv[4..7]
            float awv[4] = {aw.x, aw.y, aw.z, aw.w};
            float arv[5] = {a4.x, a4.y, a4.z, a4.w, a5};
            float bkv[4] = {bk.x, bk.y, bk.z, bk.w};
            float rv[7]  = {r0.x, r0.y, r0.z, r0.w, r1.x, r1.y, r1.z};
#pragma unroll
            for (int r = 0; r < 4; r++)
#pragma unroll
                for (int c = 0; c < 4; c++) {
                    float av = (d0 + c - r <= 0) ? arv[r] : arv[r+1];
                    s[r][c] += awv[r]*bkv[c] + av*rv[c - r + 3];
                }
        }
        __syncthreads();  // kt reads done before ps overlay writes

        // scale + key padding mask
#pragma unroll
        for (int c = 0; c < 4; c++) {
            bool mk = mask[b*T_DIM + j0 + tx*4 + c] != 0;
#pragma unroll
            for (int r = 0; r < 4; r++) {
                s[r][c] *= scale;
                if (mk) s[r][c] = -1e9f;
            }
        }

        // online softmax (row = 16 lanes sharing ty)
#pragma unroll
        for (int r = 0; r < 4; r++) {
            float mx = s[r][0];
#pragma unroll
            for (int c = 1; c < 4; c++) mx = fmaxf(mx, s[r][c]);
#pragma unroll
            for (int off = 8; off >= 1; off >>= 1)
                mx = fmaxf(mx, __shfl_xor_sync(0xffffffffu, mx, off, 16));
            float mnew = fmaxf(m[r], mx);
            float corr = __expf(m[r] - mnew);
            float4 p4;
            p4.x = __expf(s[r][0] - mnew);
            p4.y = __expf(s[r][1] - mnew);
            p4.z = __expf(s[r][2] - mnew);
            p4.w = __expf(s[r][3] - mnew);
            float rs = p4.x + p4.y + p4.z + p4.w;
            *(float4*)&ps[(ty*4+r)*QSTR + tx*4] = p4;
#pragma unroll
            for (int off = 8; off >= 1; off >>= 1)
                rs += __shfl_xor_sync(0xffffffffu, rs, off, 16);
            l[r] = l[r]*corr + rs;
            m[r] = mnew;
#pragma unroll
            for (int c = 0; c < 4; c++) acc[r][c] *= corr;
        }
        __syncthreads();

        // PV accumulate
        for (int jj = 0; jj < 64; jj++) {
            float pv[4];
#pragma unroll
            for (int r = 0; r < 4; r++) pv[r] = ps[(ty*4+r)*QSTR + jj];
            float4 vv = *(float4*)&vt[jj*64 + tx*4];
            float vvv[4] = {vv.x, vv.y, vv.z, vv.w};
#pragma unroll
            for (int r = 0; r < 4; r++)
#pragma unroll
                for (int c = 0; c < 4; c++)
                    acc[r][c] = fmaf(pv[r], vvv[c], acc[r][c]);
        }
    }

#pragma unroll
    for (int r = 0; r < 4; r++) {
        float inv = 1.f / l[r];
        int t = i0 + ty*4 + r;
#pragma unroll
        for (int c = 0; c < 4; c++)
            ctx[(long)(t*B_DIM + b)*E_DIM + h*D_DIM + tx*4 + c] = acc[r][c]*inv;
    }
}

#define ATTN_SMEM ((3*64*QSTR + 4096 + 64*RSTR) * 4)

extern "C" void kernel_launch(void* const* d_in, const int* in_sizes, int n_in,
                              void* d_out, int out_size) {
    const float* input   = (const float*)d_in[0];
    const float* pos     = (const float*)d_in[1];
    const int*   indices = (const int*)  d_in[2];
    const unsigned char* mask = (const unsigned char*)d_in[3];
    const float* in_w  = (const float*)d_in[4];
    const float* pos_w = (const float*)d_in[5];
    const float* out_w = (const float*)d_in[6];
    const float* in_b  = (const float*)d_in[7];
    const float* pos_b = (const float*)d_in[8];
    const float* out_b = (const float*)d_in[9];
    const float* r_i = (const float*)d_in[10];
    const float* s_i = (const float*)d_in[11];
    const float* r_p = (const float*)d_in[12];
    const float* s_p = (const float*)d_in[13];
    const float* r_o = (const float*)d_in[14];
    const float* s_o = (const float*)d_in[15];
    const float* rwb = (const float*)d_in[16];
    const float* rrb = (const float*)d_in[17];
    float* out = (float*)d_out;

    float *w_in, *w_pos, *w_out, *qkv, *rk, *ctx;
    cudaGetSymbolAddress((void**)&w_in,  g_w_in);
    cudaGetSymbolAddress((void**)&w_pos, g_w_pos);
    cudaGetSymbolAddress((void**)&w_out, g_w_out);
    cudaGetSymbolAddress((void**)&qkv,   g_qkv);
    cudaGetSymbolAddress((void**)&rk,    g_rk);
    cudaGetSymbolAddress((void**)&ctx,   g_ctx);

    const int thr = 256;
    build_w_kernel<<<(E_DIM*E3 + thr - 1)/thr, thr>>>(in_w,  r_i, s_i, indices, w_in,  E3);
    build_w_kernel<<<(E_DIM*E_DIM + thr - 1)/thr, thr>>>(pos_w, r_p, s_p, indices, w_pos, E_DIM);
    build_w_kernel<<<(E_DIM*E_DIM + thr - 1)/thr, thr>>>(out_w, r_o, s_o, indices, w_out, E_DIM);

    dim3 blk(16, 16);
    sgemm_bias_kernel<<<dim3(E3/64, (T_DIM*B_DIM)/64), blk>>>(input, w_in, in_b, qkv,
                                                              T_DIM*B_DIM, E3, E_DIM);
    sgemm_bias_kernel<<<dim3(E_DIM/64, T_DIM/64), blk>>>(pos, w_pos, pos_b, rk,
                                                         T_DIM, E_DIM, E_DIM);
    cudaFuncSetAttribute(attn_kernel, cudaFuncAttributeMaxDynamicSharedMemorySize, ATTN_SMEM);
    attn_kernel<<<dim3(T_DIM/64, H_DIM, B_DIM), blk, ATTN_SMEM>>>(qkv, rk, mask, rwb, rrb, ctx);

    sgemm_bias_kernel<<<dim3(E_DIM/64, (T_DIM*B_DIM)/64), blk>>>(ctx, w_out, out_b, out,
                                                                 T_DIM*B_DIM, E_DIM, E_DIM);
}

// round 8
// speedup vs baseline: 3.6854x; 1.1416x over previous
#include <cuda_runtime.h>
#include <math.h>

#define T_DIM 1024
#define B_DIM 4
#define E_DIM 1024
#define H_DIM 16
#define D_DIM 64
#define RANK_ 4
#define E3 (3*E_DIM)

// ---- device scratch ----
__device__ float g_w_in [E_DIM*E3];
__device__ float g_w_pos[E_DIM*E_DIM];
__device__ float g_w_out[E_DIM*E_DIM];
__device__ float g_qkv  [T_DIM*B_DIM*E3];
__device__ float g_rk   [T_DIM*E_DIM];
__device__ float g_ctx  [T_DIM*B_DIM*E_DIM];

// ---- W' = W + sum_r outer(r,s) ----
__global__ void build_w_kernel(const float* __restrict__ base, const float* __restrict__ rfac,
                               const float* __restrict__ sfac, const int* __restrict__ idx,
                               float* __restrict__ out, int F) {
    int lang = idx[0];
    long i = (long)blockIdx.x * blockDim.x + threadIdx.x;
    long total = (long)E_DIM * F;
    if (i >= total) return;
    int e = (int)(i / F), f = (int)(i % F);
    const float* rp = rfac + (long)lang * RANK_ * E_DIM;
    const float* sp = sfac + (long)lang * RANK_ * F;
    float acc = base[i];
#pragma unroll
    for (int r = 0; r < RANK_; r++) acc += rp[r*E_DIM + e] * sp[(long)r*F + f];
    out[i] = acc;
}

// ---- C[M,N] = A[M,K] @ B[K,N] + bias[N]; M%128==0, N%64==0, K%16==0 ----
#define BM 128
#define BN 64
#define BK 16

__global__ __launch_bounds__(256, 2)
void sgemm_bias_kernel(const float* __restrict__ A, const float* __restrict__ Bm,
                       const float* __restrict__ bias, float* __restrict__ C,
                       int M, int N, int K) {
    __shared__ float As[BK][BM+4];   // k-major, m-contiguous
    __shared__ float Bs[BK][BN+4];   // k-major, n-contiguous

    int tid = threadIdx.x;
    int tx = tid & 15;               // n-group (16 x 4 = 64)
    int ty = tid >> 4;               // m-group (16 x 8 = 128)
    int m0 = blockIdx.y*BM, n0 = blockIdx.x*BN;

    const float* Aptr = A + (long)m0*K;
    const float* Bptr = Bm + n0;

    // A: 512 float4/tile, 2 per thread. row = tid>>2 (+64), kcol4 = (tid&3)*4
    // B: 256 float4/tile, 1 per thread. krow = tid>>4, ncol4 = (tid&15)*4
    const int ar = tid >> 2, akc = (tid & 3) * 4;
    const int bkr = tid >> 4, bnc = (tid & 15) * 4;

    float4 pa0 = *(const float4*)&Aptr[(long)ar*K + akc];
    float4 pa1 = *(const float4*)&Aptr[(long)(ar+64)*K + akc];
    float4 pb  = *(const float4*)&Bptr[(long)bkr*N + bnc];

    float acc[8][4] = {};

    for (int k0 = 0; k0 < K; k0 += BK) {
        // commit prefetched tile (A transposed into k-major)
        As[akc+0][ar] = pa0.x; As[akc+1][ar] = pa0.y;
        As[akc+2][ar] = pa0.z; As[akc+3][ar] = pa0.w;
        As[akc+0][ar+64] = pa1.x; As[akc+1][ar+64] = pa1.y;
        As[akc+2][ar+64] = pa1.z; As[akc+3][ar+64] = pa1.w;
        *(float4*)&Bs[bkr][bnc] = pb;
        __syncthreads();

        if (k0 + BK < K) {
            pa0 = *(const float4*)&Aptr[(long)ar*K + (k0+BK) + akc];
            pa1 = *(const float4*)&Aptr[(long)(ar+64)*K + (k0+BK) + akc];
            pb  = *(const float4*)&Bptr[(long)(k0+BK+bkr)*N + bnc];
        }

#pragma unroll
        for (int kk = 0; kk < BK; kk++) {
            float4 a0 = *(float4*)&As[kk][ty*8];
            float4 a1 = *(float4*)&As[kk][ty*8+4];
            float4 b0 = *(float4*)&Bs[kk][tx*4];
            float av[8] = {a0.x,a0.y,a0.z,a0.w,a1.x,a1.y,a1.z,a1.w};
            float bv[4] = {b0.x,b0.y,b0.z,b0.w};
#pragma unroll
            for (int r = 0; r < 8; r++)
#pragma unroll
                for (int c = 0; c < 4; c++)
                    acc[r][c] = fmaf(av[r], bv[c], acc[r][c]);
        }
        __syncthreads();
    }

    float4 bb = *(const float4*)&bias[n0 + tx*4];
#pragma unroll
    for (int r = 0; r < 8; r++) {
        float4 o;
        o.x = acc[r][0] + bb.x;
        o.y = acc[r][1] + bb.y;
        o.z = acc[r][2] + bb.z;
        o.w = acc[r][3] + bb.w;
        *(float4*)&C[(long)(m0 + ty*8 + r)*N + n0 + tx*4] = o;
    }
}

// ---- fused relative attention, transposed (d-major) smem tiles ----
// delta = j - i:
//   delta <= 0 : s += (q_i   + rrb) . rk[T-1+delta]
//   delta == 1 : s += 0
//   delta >= 2 : s += (q_{i+1}+rrb) . rk[delta-2]
#define QSTR 68     // row stride (floats) for qw/qr/kt (d-major, lane-contig i/j)
#define RSTR 132    // row stride for rks (d-major, 127 window slots)

__global__ __launch_bounds__(256, 2)
void attn_kernel(const float* __restrict__ qkv, const float* __restrict__ rk,
                 const unsigned char* __restrict__ mask,
                 const float* __restrict__ rwb, const float* __restrict__ rrb,
                 float* __restrict__ ctx) {
    extern __shared__ float sm[];
    float* qw  = sm;                 // [64 d][QSTR]  cols ii 0..63
    float* qr  = qw  + 64*QSTR;      // [64 d][QSTR]  cols ii 0..64
    float* kt  = qr  + 64*QSTR;      // [64 d][QSTR]  cols jj 0..63 ; reused as ps
    float* vt  = kt  + 64*QSTR;      // [64 jj][64 c] row-major
    float* rks = vt  + 4096;         // [64 d][RSTR]  cols w 0..126
    float* ps  = kt;                 // overlay: [64 i][QSTR] probs

    int tx = threadIdx.x, ty = threadIdx.y;
    int tid = ty*16 + tx;
    int i0 = blockIdx.x*64;
    int h = blockIdx.y, b = blockIdx.z;
    const float scale = 0.125f;

    // Q tiles (transposed write): 65 rows x 64 d, float4 global loads
    for (int e = tid; e < 65*16; e += 256) {
        int ii = e >> 4, d4 = (e & 15) * 4;
        int t = i0 + ii;
        float4 qv = make_float4(0.f,0.f,0.f,0.f);
        if (t < T_DIM)
            qv = *(const float4*)&qkv[(long)(t*B_DIM + b)*E3 + h*D_DIM + d4];
        float4 wb = *(const float4*)&rwb[h*D_DIM + d4];
        float4 rb = *(const float4*)&rrb[h*D_DIM + d4];
        if (ii < 64) {
            qw[(d4+0)*QSTR + ii] = qv.x + wb.x;
            qw[(d4+1)*QSTR + ii] = qv.y + wb.y;
            qw[(d4+2)*QSTR + ii] = qv.z + wb.z;
            qw[(d4+3)*QSTR + ii] = qv.w + wb.w;
        }
        qr[(d4+0)*QSTR + ii] = qv.x + rb.x;
        qr[(d4+1)*QSTR + ii] = qv.y + rb.y;
        qr[(d4+2)*QSTR + ii] = qv.z + rb.z;
        qr[(d4+3)*QSTR + ii] = qv.w + rb.w;
    }

    float m[4], l[4], acc[4][4];
#pragma unroll
    for (int r = 0; r < 4; r++) {
        m[r] = -1e30f; l[r] = 0.f;
#pragma unroll
        for (int c = 0; c < 4; c++) acc[r][c] = 0.f;
    }

    const int mm15 = 15 + tx - ty;       // window float4 index: w = 4*mm15 covers delta at (r=c)-3

    for (int j0 = 0; j0 < T_DIM; j0 += 64) {
        __syncthreads();  // prev PV reads done before overwriting tiles
        // K (transposed) + V (row-major)
        for (int e = tid; e < 64*16; e += 256) {
            int jj = e >> 4, d4 = (e & 15) * 4;
            long off = (long)((j0+jj)*B_DIM + b)*E3 + h*D_DIM + d4;
            float4 kv = *(const float4*)&qkv[off + E_DIM];
            float4 vv = *(const float4*)&qkv[off + 2*E_DIM];
            kt[(d4+0)*QSTR + jj] = kv.x;
            kt[(d4+1)*QSTR + jj] = kv.y;
            kt[(d4+2)*QSTR + jj] = kv.z;
            kt[(d4+3)*QSTR + jj] = kv.w;
            *(float4*)&vt[jj*64 + d4] = vv;
        }
        // rk window (transposed): slot w covers delta = base - 63 + w
        int base = j0 - i0;
        for (int e = tid; e < 127*16; e += 256) {
            int w = e >> 4, d4 = (e & 15) * 4;
            int delta = base - 63 + w;
            float4 v = make_float4(0.f,0.f,0.f,0.f);
            if (delta <= 0)      v = *(const float4*)&rk[(long)(T_DIM - 1 + delta)*E_DIM + h*D_DIM + d4];
            else if (delta >= 2) v = *(const float4*)&rk[(long)(delta - 2)*E_DIM + h*D_DIM + d4];
            rks[(d4+0)*RSTR + w] = v.x;
            rks[(d4+1)*RSTR + w] = v.y;
            rks[(d4+2)*RSTR + w] = v.z;
            rks[(d4+3)*RSTR + w] = v.w;
        }
        __syncthreads();

        float s[4][4];
#pragma unroll
        for (int r = 0; r < 4; r++)
#pragma unroll
            for (int c = 0; c < 4; c++) s[r][c] = 0.f;

        const int d0 = base + 4*(tx - ty);  // delta at (r=c)

        for (int d = 0; d < 64; d++) {
            float4 aw = *(float4*)&qw[d*QSTR + ty*4];
            float4 a4 = *(float4*)&qr[d*QSTR + ty*4];
            float  a5 = qr[d*QSTR + ty*4 + 4];
            float4 bk = *(float4*)&kt[d*QSTR + tx*4];
            float4 r0 = *(float4*)&rks[d*RSTR + 4*mm15];       // rv[0..3] (o-3 = -3..0)
            float4 r1 = *(float4*)&rks[d*RSTR + 4*mm15 + 4];   // rv[4..7]
            float awv[4] = {aw.x, aw.y, aw.z, aw.w};
            float arv[5] = {a4.x, a4.y, a4.z, a4.w, a5};
            float bkv[4] = {bk.x, bk.y, bk.z, bk.w};
            float rv[7]  = {r0.x, r0.y, r0.z, r0.w, r1.x, r1.y, r1.z};
#pragma unroll
            for (int r = 0; r < 4; r++)
#pragma unroll
                for (int c = 0; c < 4; c++) {
                    float av = (d0 + c - r <= 0) ? arv[r] : arv[r+1];
                    s[r][c] += awv[r]*bkv[c] + av*rv[c - r + 3];
                }
        }
        __syncthreads();  // kt reads done before ps overlay writes

        // scale + key padding mask
#pragma unroll
        for (int c = 0; c < 4; c++) {
            bool mk = mask[b*T_DIM + j0 + tx*4 + c] != 0;
#pragma unroll
            for (int r = 0; r < 4; r++) {
                s[r][c] *= scale;
                if (mk) s[r][c] = -1e9f;
            }
        }

        // online softmax (row = 16 lanes sharing ty)
#pragma unroll
        for (int r = 0; r < 4; r++) {
            float mx = s[r][0];
#pragma unroll
            for (int c = 1; c < 4; c++) mx = fmaxf(mx, s[r][c]);
#pragma unroll
            for (int off = 8; off >= 1; off >>= 1)
                mx = fmaxf(mx, __shfl_xor_sync(0xffffffffu, mx, off, 16));
            float mnew = fmaxf(m[r], mx);
            float corr = __expf(m[r] - mnew);
            float4 p4;
            p4.x = __expf(s[r][0] - mnew);
            p4.y = __expf(s[r][1] - mnew);
            p4.z = __expf(s[r][2] - mnew);
            p4.w = __expf(s[r][3] - mnew);
            float rs = p4.x + p4.y + p4.z + p4.w;
            *(float4*)&ps[(ty*4+r)*QSTR + tx*4] = p4;
#pragma unroll
            for (int off = 8; off >= 1; off >>= 1)
                rs += __shfl_xor_sync(0xffffffffu, rs, off, 16);
            l[r] = l[r]*corr + rs;
            m[r] = mnew;
#pragma unroll
            for (int c = 0; c < 4; c++) acc[r][c] *= corr;
        }
        __syncthreads();

        // PV accumulate
        for (int jj = 0; jj < 64; jj++) {
            float pv[4];
#pragma unroll
            for (int r = 0; r < 4; r++) pv[r] = ps[(ty*4+r)*QSTR + jj];
            float4 vv = *(float4*)&vt[jj*64 + tx*4];
            float vvv[4] = {vv.x, vv.y, vv.z, vv.w};
#pragma unroll
            for (int r = 0; r < 4; r++)
#pragma unroll
                for (int c = 0; c < 4; c++)
                    acc[r][c] = fmaf(pv[r], vvv[c], acc[r][c]);
        }
    }

#pragma unroll
    for (int r = 0; r < 4; r++) {
        float inv = 1.f / l[r];
        int t = i0 + ty*4 + r;
#pragma unroll
        for (int c = 0; c < 4; c++)
            ctx[(long)(t*B_DIM + b)*E_DIM + h*D_DIM + tx*4 + c] = acc[r][c]*inv;
    }
}

#define ATTN_SMEM ((3*64*QSTR + 4096 + 64*RSTR) * 4)

extern "C" void kernel_launch(void* const* d_in, const int* in_sizes, int n_in,
                              void* d_out, int out_size) {
    const float* input   = (const float*)d_in[0];
    const float* pos     = (const float*)d_in[1];
    const int*   indices = (const int*)  d_in[2];
    const unsigned char* mask = (const unsigned char*)d_in[3];
    const float* in_w  = (const float*)d_in[4];
    const float* pos_w = (const float*)d_in[5];
    const float* out_w = (const float*)d_in[6];
    const float* in_b  = (const float*)d_in[7];
    const float* pos_b = (const float*)d_in[8];
    const float* out_b = (const float*)d_in[9];
    const float* r_i = (const float*)d_in[10];
    const float* s_i = (const float*)d_in[11];
    const float* r_p = (const float*)d_in[12];
    const float* s_p = (const float*)d_in[13];
    const float* r_o = (const float*)d_in[14];
    const float* s_o = (const float*)d_in[15];
    const float* rwb = (const float*)d_in[16];
    const float* rrb = (const float*)d_in[17];
    float* out = (float*)d_out;

    float *w_in, *w_pos, *w_out, *qkv, *rk, *ctx;
    cudaGetSymbolAddress((void**)&w_in,  g_w_in);
    cudaGetSymbolAddress((void**)&w_pos, g_w_pos);
    cudaGetSymbolAddress((void**)&w_out, g_w_out);
    cudaGetSymbolAddress((void**)&qkv,   g_qkv);
    cudaGetSymbolAddress((void**)&rk,    g_rk);
    cudaGetSymbolAddress((void**)&ctx,   g_ctx);

    const int thr = 256;
    build_w_kernel<<<(E_DIM*E3 + thr - 1)/thr, thr>>>(in_w,  r_i, s_i, indices, w_in,  E3);
    build_w_kernel<<<(E_DIM*E_DIM + thr - 1)/thr, thr>>>(pos_w, r_p, s_p, indices, w_pos, E_DIM);
    build_w_kernel<<<(E_DIM*E_DIM + thr - 1)/thr, thr>>>(out_w, r_o, s_o, indices, w_out, E_DIM);

    // qkv = input @ w_in + bias   [4096,1024]x[1024,3072]
    sgemm_bias_kernel<<<dim3(E3/BN, (T_DIM*B_DIM)/BM), 256>>>(input, w_in, in_b, qkv,
                                                              T_DIM*B_DIM, E3, E_DIM);
    // r_head_k = pos @ w_pos + bias  [1024,1024]x[1024,1024]
    sgemm_bias_kernel<<<dim3(E_DIM/BN, T_DIM/BM), 256>>>(pos, w_pos, pos_b, rk,
                                                         T_DIM, E_DIM, E_DIM);
    cudaFuncSetAttribute(attn_kernel, cudaFuncAttributeMaxDynamicSharedMemorySize, ATTN_SMEM);
    attn_kernel<<<dim3(T_DIM/64, H_DIM, B_DIM), dim3(16,16), ATTN_SMEM>>>(qkv, rk, mask, rwb, rrb, ctx);

    // out = ctx @ w_out + bias   [4096,1024]x[1024,1024]
    sgemm_bias_kernel<<<dim3(E_DIM/BN, (T_DIM*B_DIM)/BM), 256>>>(ctx, w_out, out_b, out,
                                                                 T_DIM*B_DIM, E_DIM, E_DIM);
}

// round 10
// speedup vs baseline: 4.4705x; 1.2130x over previous
#include <cuda_runtime.h>
#include <cuda_bf16.h>
#include <math.h>
#include <stdint.h>

#define T_DIM 1024
#define B_DIM 4
#define E_DIM 1024
#define H_DIM 16
#define D_DIM 64
#define RANK_ 4
#define E3 (3*E_DIM)

// ---- device scratch ----
__device__ float g_qkv  [T_DIM*B_DIM*E3];
__device__ float g_rk   [T_DIM*E_DIM];
__device__ float g_ctx  [T_DIM*B_DIM*E_DIM];

__device__ __align__(16) __nv_bfloat16 g_in_hi [T_DIM*B_DIM*E_DIM];
__device__ __align__(16) __nv_bfloat16 g_in_lo [T_DIM*B_DIM*E_DIM];
__device__ __align__(16) __nv_bfloat16 g_pos_hi[T_DIM*E_DIM];
__device__ __align__(16) __nv_bfloat16 g_pos_lo[T_DIM*E_DIM];
__device__ __align__(16) __nv_bfloat16 g_ctx_hi[T_DIM*B_DIM*E_DIM];
__device__ __align__(16) __nv_bfloat16 g_ctx_lo[T_DIM*B_DIM*E_DIM];
__device__ __align__(16) __nv_bfloat16 g_win_hi [E3*E_DIM];   // [n][k]
__device__ __align__(16) __nv_bfloat16 g_win_lo [E3*E_DIM];
__device__ __align__(16) __nv_bfloat16 g_wpos_hi[E_DIM*E_DIM];
__device__ __align__(16) __nv_bfloat16 g_wpos_lo[E_DIM*E_DIM];
__device__ __align__(16) __nv_bfloat16 g_wout_hi[E_DIM*E_DIM];
__device__ __align__(16) __nv_bfloat16 g_wout_lo[E_DIM*E_DIM];

// ---- warp-level bf16 MMA (family-common, works at target sm_100) ----
__device__ __forceinline__ void mma16816(float* c, const uint32_t* a, const uint32_t* b){
    asm volatile(
        "mma.sync.aligned.m16n8k16.row.col.f32.bf16.bf16.f32 "
        "{%0,%1,%2,%3}, {%4,%5,%6,%7}, {%8,%9}, {%0,%1,%2,%3};"
        : "+f"(c[0]), "+f"(c[1]), "+f"(c[2]), "+f"(c[3])
        : "r"(a[0]), "r"(a[1]), "r"(a[2]), "r"(a[3]), "r"(b[0]), "r"(b[1]));
}

// ---- W' = W + sum_r outer(r,s); output TRANSPOSED [f][e] as bf16 hi/lo ----
__global__ void build_w_bf16(const float* __restrict__ base, const float* __restrict__ rfac,
                             const float* __restrict__ sfac, const int* __restrict__ idx,
                             __nv_bfloat16* __restrict__ whi, __nv_bfloat16* __restrict__ wlo,
                             int F) {
    int lang = idx[0];
    long i = (long)blockIdx.x * blockDim.x + threadIdx.x;
    long total = (long)F * (E_DIM/8);
    if (i >= total) return;
    int f = (int)(i % F);
    int e0 = (int)(i / F) * 8;
    const float* rp = rfac + (long)lang * RANK_ * E_DIM;
    const float* sp = sfac + (long)lang * RANK_ * F;
    float sv[RANK_];
#pragma unroll
    for (int r = 0; r < RANK_; r++) sv[r] = sp[(long)r*F + f];
    __nv_bfloat16 h8[8], l8[8];
#pragma unroll
    for (int j = 0; j < 8; j++) {
        int e = e0 + j;
        float v = base[(long)e*F + f];
#pragma unroll
        for (int r = 0; r < RANK_; r++) v = fmaf(rp[r*E_DIM + e], sv[r], v);
        __nv_bfloat16 h = __float2bfloat16(v);
        h8[j] = h;
        l8[j] = __float2bfloat16(v - __bfloat162float(h));
    }
    *(uint4*)&whi[(long)f*E_DIM + e0] = *(uint4*)h8;
    *(uint4*)&wlo[(long)f*E_DIM + e0] = *(uint4*)l8;
}

// ---- fp32 -> bf16 hi/lo split ----
__global__ void conv_bf16(const float* __restrict__ x, __nv_bfloat16* __restrict__ hi,
                          __nv_bfloat16* __restrict__ lo, int n) {
    int i = (blockIdx.x*blockDim.x + threadIdx.x) * 4;
    if (i >= n) return;
    float4 v = *(const float4*)&x[i];
    float vv[4] = {v.x, v.y, v.z, v.w};
    __nv_bfloat16 h4[4], l4[4];
#pragma unroll
    for (int j = 0; j < 4; j++) {
        __nv_bfloat16 h = __float2bfloat16(vv[j]);
        h4[j] = h;
        l4[j] = __float2bfloat16(vv[j] - __bfloat162float(h));
    }
    *(uint2*)&hi[i] = *(uint2*)h4;
    *(uint2*)&lo[i] = *(uint2*)l4;
}

// ---- HMMA bf16-split GEMM: C[M,N] = A[M,K] @ B[N,K]^T + bias ----
// Tile: 128(M) x 64(N), K-chunk 32, 8 warps (4M x 2N), warp tile 32x32.
#define SA 56   // smem row stride in bf16 (112B: 16B-aligned, 8-row bank-distinct)

__global__ __launch_bounds__(256, 2)
void gemm_mma(const __nv_bfloat16* __restrict__ Ahi, const __nv_bfloat16* __restrict__ Alo,
              const __nv_bfloat16* __restrict__ Bhi, const __nv_bfloat16* __restrict__ Blo,
              const float* __restrict__ bias, float* __restrict__ C, int N_) {
    __shared__ __align__(16) __nv_bfloat16 sAh[128*SA];
    __shared__ __align__(16) __nv_bfloat16 sAl[128*SA];
    __shared__ __align__(16) __nv_bfloat16 sBh[64*SA];
    __shared__ __align__(16) __nv_bfloat16 sBl[64*SA];

    const int K = E_DIM;
    int tid = threadIdx.x;
    int wid = tid >> 5, lid = tid & 31;
    int warpM = wid & 3, warpN = wid >> 2;
    long m0 = (long)blockIdx.y * 128, n0 = (long)blockIdx.x * 64;

    int gRow = lid >> 2;          // 0..7
    int cPair = (lid & 3) * 2;    // 0,2,4,6

    // global load positions
    const int ap0 = tid, ap1 = tid + 256;          // A: 512 uint4 slots (128 rows x 4)
    const int ar0 = ap0 >> 2, aq0 = ap0 & 3;
    const int ar1 = ap1 >> 2, aq1 = ap1 & 3;
    const int br = tid >> 2, bq = tid & 3;          // B: 256 slots (64 rows x 4)

    float acc[2][4][4];
#pragma unroll
    for (int mt = 0; mt < 2; mt++)
#pragma unroll
        for (int nt = 0; nt < 4; nt++)
#pragma unroll
            for (int q = 0; q < 4; q++) acc[mt][nt][q] = 0.f;

    // prefetch chunk 0
    uint4 pah0 = *(const uint4*)&Ahi[(m0+ar0)*K + aq0*8];
    uint4 pah1 = *(const uint4*)&Ahi[(m0+ar1)*K + aq1*8];
    uint4 pal0 = *(const uint4*)&Alo[(m0+ar0)*K + aq0*8];
    uint4 pal1 = *(const uint4*)&Alo[(m0+ar1)*K + aq1*8];
    uint4 pbh  = *(const uint4*)&Bhi[(n0+br)*K + bq*8];
    uint4 pbl  = *(const uint4*)&Blo[(n0+br)*K + bq*8];

    for (int kc = 0; kc < K; kc += 32) {
        *(uint4*)&sAh[ar0*SA + aq0*8] = pah0;
        *(uint4*)&sAh[ar1*SA + aq1*8] = pah1;
        *(uint4*)&sAl[ar0*SA + aq0*8] = pal0;
        *(uint4*)&sAl[ar1*SA + aq1*8] = pal1;
        *(uint4*)&sBh[br*SA + bq*8] = pbh;
        *(uint4*)&sBl[br*SA + bq*8] = pbl;
        __syncthreads();

        if (kc + 32 < K) {
            int kn = kc + 32;
            pah0 = *(const uint4*)&Ahi[(m0+ar0)*K + kn + aq0*8];
            pah1 = *(const uint4*)&Ahi[(m0+ar1)*K + kn + aq1*8];
            pal0 = *(const uint4*)&Alo[(m0+ar0)*K + kn + aq0*8];
            pal1 = *(const uint4*)&Alo[(m0+ar1)*K + kn + aq1*8];
            pbh  = *(const uint4*)&Bhi[(n0+br)*K + kn + bq*8];
            pbl  = *(const uint4*)&Blo[(n0+br)*K + kn + bq*8];
        }

#pragma unroll
        for (int ks = 0; ks < 2; ks++) {
            int kb = ks * 16;
            uint32_t ah[2][4], al[2][4], bh[4][2], bl[4][2];
#pragma unroll
            for (int mt = 0; mt < 2; mt++) {
                int r = warpM*32 + mt*16 + gRow;
                ah[mt][0] = *(uint32_t*)&sAh[r*SA + kb + cPair];
                ah[mt][1] = *(uint32_t*)&sAh[(r+8)*SA + kb + cPair];
                ah[mt][2] = *(uint32_t*)&sAh[r*SA + kb + cPair + 8];
                ah[mt][3] = *(uint32_t*)&sAh[(r+8)*SA + kb + cPair + 8];
                al[mt][0] = *(uint32_t*)&sAl[r*SA + kb + cPair];
                al[mt][1] = *(uint32_t*)&sAl[(r+8)*SA + kb + cPair];
                al[mt][2] = *(uint32_t*)&sAl[r*SA + kb + cPair + 8];
                al[mt][3] = *(uint32_t*)&sAl[(r+8)*SA + kb + cPair + 8];
            }
#pragma unroll
            for (int nt = 0; nt < 4; nt++) {
                int n = warpN*32 + nt*8 + gRow;
                bh[nt][0] = *(uint32_t*)&sBh[n*SA + kb + cPair];
                bh[nt][1] = *(uint32_t*)&sBh[n*SA + kb + cPair + 8];
                bl[nt][0] = *(uint32_t*)&sBl[n*SA + kb + cPair];
                bl[nt][1] = *(uint32_t*)&sBl[n*SA + kb + cPair + 8];
            }
#pragma unroll
            for (int mt = 0; mt < 2; mt++)
#pragma unroll
                for (int nt = 0; nt < 4; nt++) {
                    mma16816(acc[mt][nt], ah[mt], bh[nt]);
                    mma16816(acc[mt][nt], ah[mt], bl[nt]);
                    mma16816(acc[mt][nt], al[mt], bh[nt]);
                }
        }
        __syncthreads();
    }

    // epilogue: acc layout c0,c1=(row, col..col+1), c2,c3=(row+8, ...)
#pragma unroll
    for (int mt = 0; mt < 2; mt++) {
        long r0 = m0 + warpM*32 + mt*16 + gRow;
#pragma unroll
        for (int nt = 0; nt < 4; nt++) {
            long n = n0 + warpN*32 + nt*8 + cPair;
            float2 bia = *(const float2*)&bias[n];
            float2 o0 = { acc[mt][nt][0] + bia.x, acc[mt][nt][1] + bia.y };
            float2 o1 = { acc[mt][nt][2] + bia.x, acc[mt][nt][3] + bia.y };
            *(float2*)&C[r0*N_ + n] = o0;
            *(float2*)&C[(r0+8)*N_ + n] = o1;
        }
    }
}

// ---- fused relative attention (unchanged, passing) ----
#define QSTR 68
#define RSTR 132

__global__ __launch_bounds__(256, 2)
void attn_kernel(const float* __restrict__ qkv, const float* __restrict__ rk,
                 const unsigned char* __restrict__ mask,
                 const float* __restrict__ rwb, const float* __restrict__ rrb,
                 float* __restrict__ ctx) {
    extern __shared__ float sm[];
    float* qw  = sm;
    float* qr  = qw  + 64*QSTR;
    float* kt  = qr  + 64*QSTR;
    float* vt  = kt  + 64*QSTR;
    float* rks = vt  + 4096;
    float* ps  = kt;

    int tx = threadIdx.x, ty = threadIdx.y;
    int tid = ty*16 + tx;
    int i0 = blockIdx.x*64;
    int h = blockIdx.y, b = blockIdx.z;
    const float scale = 0.125f;

    for (int e = tid; e < 65*16; e += 256) {
        int ii = e >> 4, d4 = (e & 15) * 4;
        int t = i0 + ii;
        float4 qv = make_float4(0.f,0.f,0.f,0.f);
        if (t < T_DIM)
            qv = *(const float4*)&qkv[(long)(t*B_DIM + b)*E3 + h*D_DIM + d4];
        float4 wb = *(const float4*)&rwb[h*D_DIM + d4];
        float4 rb = *(const float4*)&rrb[h*D_DIM + d4];
        if (ii < 64) {
            qw[(d4+0)*QSTR + ii] = qv.x + wb.x;
            qw[(d4+1)*QSTR + ii] = qv.y + wb.y;
            qw[(d4+2)*QSTR + ii] = qv.z + wb.z;
            qw[(d4+3)*QSTR + ii] = qv.w + wb.w;
        }
        qr[(d4+0)*QSTR + ii] = qv.x + rb.x;
        qr[(d4+1)*QSTR + ii] = qv.y + rb.y;
        qr[(d4+2)*QSTR + ii] = qv.z + rb.z;
        qr[(d4+3)*QSTR + ii] = qv.w + rb.w;
    }

    float m[4], l[4], acc[4][4];
#pragma unroll
    for (int r = 0; r < 4; r++) {
        m[r] = -1e30f; l[r] = 0.f;
#pragma unroll
        for (int c = 0; c < 4; c++) acc[r][c] = 0.f;
    }

    const int mm15 = 15 + tx - ty;

    for (int j0 = 0; j0 < T_DIM; j0 += 64) {
        __syncthreads();
        for (int e = tid; e < 64*16; e += 256) {
            int jj = e >> 4, d4 = (e & 15) * 4;
            long off = (long)((j0+jj)*B_DIM + b)*E3 + h*D_DIM + d4;
            float4 kv = *(const float4*)&qkv[off + E_DIM];
            float4 vv = *(const float4*)&qkv[off + 2*E_DIM];
            kt[(d4+0)*QSTR + jj] = kv.x;
            kt[(d4+1)*QSTR + jj] = kv.y;
            kt[(d4+2)*QSTR + jj] = kv.z;
            kt[(d4+3)*QSTR + jj] = kv.w;
            *(float4*)&vt[jj*64 + d4] = vv;
        }
        int base = j0 - i0;
        for (int e = tid; e < 127*16; e += 256) {
            int w = e >> 4, d4 = (e & 15) * 4;
            int delta = base - 63 + w;
            float4 v = make_float4(0.f,0.f,0.f,0.f);
            if (delta <= 0)      v = *(const float4*)&rk[(long)(T_DIM - 1 + delta)*E_DIM + h*D_DIM + d4];
            else if (delta >= 2) v = *(const float4*)&rk[(long)(delta - 2)*E_DIM + h*D_DIM + d4];
            rks[(d4+0)*RSTR + w] = v.x;
            rks[(d4+1)*RSTR + w] = v.y;
            rks[(d4+2)*RSTR + w] = v.z;
            rks[(d4+3)*RSTR + w] = v.w;
        }
        __syncthreads();

        float s[4][4];
#pragma unroll
        for (int r = 0; r < 4; r++)
#pragma unroll
            for (int c = 0; c < 4; c++) s[r][c] = 0.f;

        const int d0 = base + 4*(tx - ty);

        for (int d = 0; d < 64; d++) {
            float4 aw = *(float4*)&qw[d*QSTR + ty*4];
            float4 a4 = *(float4*)&qr[d*QSTR + ty*4];
            float  a5 = qr[d*QSTR + ty*4 + 4];
            float4 bk = *(float4*)&kt[d*QSTR + tx*4];
            float4 r0 = *(float4*)&rks[d*RSTR + 4*mm15];
            float4 r1 = *(float4*)&rks[d*RSTR + 4*mm15 + 4];
            float awv[4] = {aw.x, aw.y, aw.z, aw.w};
            float arv[5] = {a4.x, a4.y, a4.z, a4.w, a5};
            float bkv[4] = {bk.x, bk.y, bk.z, bk.w};
            float rv[7]  = {r0.x, r0.y, r0.z, r0.w, r1.x, r1.y, r1.z};
#pragma unroll
            for (int r = 0; r < 4; r++)
#pragma unroll
                for (int c = 0; c < 4; c++) {
                    float av = (d0 + c - r <= 0) ? arv[r] : arv[r+1];
                    s[r][c] += awv[r]*bkv[c] + av*rv[c - r + 3];
                }
        }
        __syncthreads();

#pragma unroll
        for (int c = 0; c < 4; c++) {
            bool mk = mask[b*T_DIM + j0 + tx*4 + c] != 0;
#pragma unroll
            for (int r = 0; r < 4; r++) {
                s[r][c] *= scale;
                if (mk) s[r][c] = -1e9f;
            }
        }

#pragma unroll
        for (int r = 0; r < 4; r++) {
            float mx = s[r][0];
#pragma unroll
            for (int c = 1; c < 4; c++) mx = fmaxf(mx, s[r][c]);
#pragma unroll
            for (int off = 8; off >= 1; off >>= 1)
                mx = fmaxf(mx, __shfl_xor_sync(0xffffffffu, mx, off, 16));
            float mnew = fmaxf(m[r], mx);
            float corr = __expf(m[r] - mnew);
            float4 p4;
            p4.x = __expf(s[r][0] - mnew);
            p4.y = __expf(s[r][1] - mnew);
            p4.z = __expf(s[r][2] - mnew);
            p4.w = __expf(s[r][3] - mnew);
            float rs = p4.x + p4.y + p4.z + p4.w;
            *(float4*)&ps[(ty*4+r)*QSTR + tx*4] = p4;
#pragma unroll
            for (int off = 8; off >= 1; off >>= 1)
                rs += __shfl_xor_sync(0xffffffffu, rs, off, 16);
            l[r] = l[r]*corr + rs;
            m[r] = mnew;
#pragma unroll
            for (int c = 0; c < 4; c++) acc[r][c] *= corr;
        }
        __syncthreads();

        for (int jj = 0; jj < 64; jj++) {
            float pv[4];
#pragma unroll
            for (int r = 0; r < 4; r++) pv[r] = ps[(ty*4+r)*QSTR + jj];
            float4 vv = *(float4*)&vt[jj*64 + tx*4];
            float vvv[4] = {vv.x, vv.y, vv.z, vv.w};
#pragma unroll
            for (int r = 0; r < 4; r++)
#pragma unroll
                for (int c = 0; c < 4; c++)
                    acc[r][c] = fmaf(pv[r], vvv[c], acc[r][c]);
        }
    }

#pragma unroll
    for (int r = 0; r < 4; r++) {
        float inv = 1.f / l[r];
        int t = i0 + ty*4 + r;
#pragma unroll
        for (int c = 0; c < 4; c++)
            ctx[(long)(t*B_DIM + b)*E_DIM + h*D_DIM + tx*4 + c] = acc[r][c]*inv;
    }
}

#define ATTN_SMEM ((3*64*QSTR + 4096 + 64*RSTR) * 4)

extern "C" void kernel_launch(void* const* d_in, const int* in_sizes, int n_in,
                              void* d_out, int out_size) {
    const float* input   = (const float*)d_in[0];
    const float* pos     = (const float*)d_in[1];
    const int*   indices = (const int*)  d_in[2];
    const unsigned char* mask = (const unsigned char*)d_in[3];
    const float* in_w  = (const float*)d_in[4];
    const float* pos_w = (const float*)d_in[5];
    const float* out_w = (const float*)d_in[6];
    const float* in_b  = (const float*)d_in[7];
    const float* pos_b = (const float*)d_in[8];
    const float* out_b = (const float*)d_in[9];
    const float* r_i = (const float*)d_in[10];
    const float* s_i = (const float*)d_in[11];
    const float* r_p = (const float*)d_in[12];
    const float* s_p = (const float*)d_in[13];
    const float* r_o = (const float*)d_in[14];
    const float* s_o = (const float*)d_in[15];
    const float* rwb = (const float*)d_in[16];
    const float* rrb = (const float*)d_in[17];
    float* out = (float*)d_out;

    float *qkv, *rk, *ctx;
    __nv_bfloat16 *in_hi, *in_lo, *pos_hi, *pos_lo, *ctx_hi, *ctx_lo;
    __nv_bfloat16 *win_hi, *win_lo, *wpos_hi, *wpos_lo, *wout_hi, *wout_lo;
    cudaGetSymbolAddress((void**)&qkv,   g_qkv);
    cudaGetSymbolAddress((void**)&rk,    g_rk);
    cudaGetSymbolAddress((void**)&ctx,   g_ctx);
    cudaGetSymbolAddress((void**)&in_hi, g_in_hi);
    cudaGetSymbolAddress((void**)&in_lo, g_in_lo);
    cudaGetSymbolAddress((void**)&pos_hi,g_pos_hi);
    cudaGetSymbolAddress((void**)&pos_lo,g_pos_lo);
    cudaGetSymbolAddress((void**)&ctx_hi,g_ctx_hi);
    cudaGetSymbolAddress((void**)&ctx_lo,g_ctx_lo);
    cudaGetSymbolAddress((void**)&win_hi,g_win_hi);
    cudaGetSymbolAddress((void**)&win_lo,g_win_lo);
    cudaGetSymbolAddress((void**)&wpos_hi,g_wpos_hi);
    cudaGetSymbolAddress((void**)&wpos_lo,g_wpos_lo);
    cudaGetSymbolAddress((void**)&wout_hi,g_wout_hi);
    cudaGetSymbolAddress((void**)&wout_lo,g_wout_lo);

    const int thr = 256;
    build_w_bf16<<<(E3*(E_DIM/8) + thr-1)/thr, thr>>>(in_w,  r_i, s_i, indices, win_hi,  win_lo,  E3);
    build_w_bf16<<<(E_DIM*(E_DIM/8) + thr-1)/thr, thr>>>(pos_w, r_p, s_p, indices, wpos_hi, wpos_lo, E_DIM);
    build_w_bf16<<<(E_DIM*(E_DIM/8) + thr-1)/thr, thr>>>(out_w, r_o, s_o, indices, wout_hi, wout_lo, E_DIM);
    conv_bf16<<<(T_DIM*B_DIM*E_DIM/4 + thr-1)/thr, thr>>>(input, in_hi, in_lo, T_DIM*B_DIM*E_DIM);
    conv_bf16<<<(T_DIM*E_DIM/4 + thr-1)/thr, thr>>>(pos, pos_hi, pos_lo, T_DIM*E_DIM);

    // qkv = input @ w_in + bias : [4096,1024] x [3072,1024]^T
    gemm_mma<<<dim3(E3/64, (T_DIM*B_DIM)/128), 256>>>(in_hi, in_lo, win_hi, win_lo, in_b, qkv, E3);
    // rk = pos @ w_pos + bias : [1024,1024] x [1024,1024]^T
    gemm_mma<<<dim3(E_DIM/64, T_DIM/128), 256>>>(pos_hi, pos_lo, wpos_hi, wpos_lo, pos_b, rk, E_DIM);

    cudaFuncSetAttribute(attn_kernel, cudaFuncAttributeMaxDynamicSharedMemorySize, ATTN_SMEM);
    attn_kernel<<<dim3(T_DIM/64, H_DIM, B_DIM), dim3(16,16), ATTN_SMEM>>>(qkv, rk, mask, rwb, rrb, ctx);

    conv_bf16<<<(T_DIM*B_DIM*E_DIM/4 + thr-1)/thr, thr>>>(ctx, ctx_hi, ctx_lo, T_DIM*B_DIM*E_DIM);
    // out = ctx @ w_out + bias : [4096,1024] x [1024,1024]^T
    gemm_mma<<<dim3(E_DIM/64, (T_DIM*B_DIM)/128), 256>>>(ctx_hi, ctx_lo, wout_hi, wout_lo, out_b, out, E_DIM);
}